// round 11
// baseline (speedup 1.0000x reference)
#include <cuda_runtime.h>
#include <cuda_bf16.h>
#include <math.h>
#include <stdint.h>

#define T_TOKENS   8192
#define DIM        1024
#define HIDDEN     2048
#define NEXP       8
#define TOPK       2
#define NROWS      (T_TOKENS * TOPK)   // 16384

#define BM 128
#define BN 128
#define BK 32                      // bf16 k-elements per stage
#define ROWB 80                    // padded row stride (64B data + 16B pad)
#define TILE_SZ (BM * ROWB)        // 10240 B per operand tile
#define STAGE   (4 * TILE_SZ)      // Ahi, Alo, Bhi, Blo
#define NSTAGE  3
#define SMEM_DYN (NSTAGE * STAGE)  // 122880 B
#define MAXTILES 136

// ---------------- scratch ----------------
__device__ __nv_bfloat16 g_w1hi[(size_t)NEXP * HIDDEN * DIM];
__device__ __nv_bfloat16 g_w1lo[(size_t)NEXP * HIDDEN * DIM];
__device__ __nv_bfloat16 g_w2hi[(size_t)NEXP * DIM * HIDDEN];
__device__ __nv_bfloat16 g_w2lo[(size_t)NEXP * DIM * HIDDEN];
__device__ __nv_bfloat16 g_xhi[(size_t)T_TOKENS * DIM];
__device__ __nv_bfloat16 g_xlo[(size_t)T_TOKENS * DIM];
__device__ __nv_bfloat16 g_hhi[(size_t)NROWS * HIDDEN];
__device__ __nv_bfloat16 g_hlo[(size_t)NROWS * HIDDEN];
__device__ float    g_ybuf[(size_t)NROWS * DIM];
__device__ int   g_counts[NEXP];
__device__ int   g_cursor[NEXP];
__device__ int   g_offsets[NEXP];
__device__ float g_psum[NEXP];
__device__ int   g_topk_idx[T_TOKENS * TOPK];
__device__ float g_topk_gate[T_TOKENS * TOPK];
__device__ int   g_row_token[NROWS];
__device__ int   g_token_row[T_TOKENS * TOPK];
__device__ int   g_tile_expert[MAXTILES];
__device__ int   g_tile_row[MAXTILES];
__device__ int   g_tile_m[MAXTILES];
__device__ int   g_ntiles;

// ---------------- helpers ----------------
__device__ __forceinline__ uint32_t s2u(const void* p) {
    uint32_t a;
    asm("{ .reg .u64 t; cvta.to.shared.u64 t, %1; cvt.u32.u64 %0, t; }" : "=r"(a) : "l"(p));
    return a;
}

#define LDSM4(r, addr) \
    asm volatile("ldmatrix.sync.aligned.m8n8.x4.shared.b16 {%0,%1,%2,%3}, [%4];" \
        : "=r"((r)[0]), "=r"((r)[1]), "=r"((r)[2]), "=r"((r)[3]) : "r"(addr) : "memory")

#define MMA16816(d, a, b0, b1) \
    asm volatile("mma.sync.aligned.m16n8k16.row.col.f32.bf16.bf16.f32 " \
        "{%0,%1,%2,%3}, {%4,%5,%6,%7}, {%8,%9}, {%0,%1,%2,%3};" \
        : "+f"((d)[0]), "+f"((d)[1]), "+f"((d)[2]), "+f"((d)[3]) \
        : "r"((a)[0]), "r"((a)[1]), "r"((a)[2]), "r"((a)[3]), "r"(b0), "r"(b1))

#define CPASYNC16(saddr, gptr, sz) \
    asm volatile("cp.async.cg.shared.global [%0], [%1], 16, %2;" \
        :: "r"(saddr), "l"(gptr), "r"(sz) : "memory")
#define CPCOMMIT() asm volatile("cp.async.commit_group;" ::: "memory")
#define CPWAIT1()  asm volatile("cp.async.wait_group 1;" ::: "memory")

__device__ __forceinline__ float gelu_exact(float v) {
    return 0.5f * v * (1.f + erff(v * 0.70710678118654752f));
}

// ---------------- pre-split: fp32 -> bf16 hi + bf16 lo residual ----------------
// which: 0=w1, 1=w2, 2=x
__global__ void split_kernel(const float4* __restrict__ src, int which, int n4) {
    __nv_bfloat16 *dh, *dl;
    if (which == 0)      { dh = g_w1hi; dl = g_w1lo; }
    else if (which == 1) { dh = g_w2hi; dl = g_w2lo; }
    else                 { dh = g_xhi;  dl = g_xlo;  }
    int stride = gridDim.x * blockDim.x;
    for (int i = blockIdx.x * blockDim.x + threadIdx.x; i < n4; i += stride) {
        float4 f = src[i];
        uint32_t h0, h1, l0, l1;
        asm("cvt.rn.bf16x2.f32 %0, %1, %2;" : "=r"(h0) : "f"(f.y), "f"(f.x));
        asm("cvt.rn.bf16x2.f32 %0, %1, %2;" : "=r"(h1) : "f"(f.w), "f"(f.z));
        float rx = f.x - __uint_as_float(h0 << 16);
        float ry = f.y - __uint_as_float(h0 & 0xffff0000u);
        float rz = f.z - __uint_as_float(h1 << 16);
        float rw = f.w - __uint_as_float(h1 & 0xffff0000u);
        asm("cvt.rn.bf16x2.f32 %0, %1, %2;" : "=r"(l0) : "f"(ry), "f"(rx));
        asm("cvt.rn.bf16x2.f32 %0, %1, %2;" : "=r"(l1) : "f"(rw), "f"(rz));
        *(uint2*)(dh + (size_t)i * 4) = make_uint2(h0, h1);
        *(uint2*)(dl + (size_t)i * 4) = make_uint2(l0, l1);
    }
}

// ---------------- small kernels (unchanged, verified passing) ----------------
__global__ void init_kernel() {
    int i = threadIdx.x;
    if (i < NEXP) { g_counts[i] = 0; g_cursor[i] = 0; g_psum[i] = 0.f; }
}

__global__ void router_kernel(const float* __restrict__ x,
                              const float* __restrict__ rw) {
    __shared__ float s_rw[NEXP * DIM];
    for (int i = threadIdx.x; i < NEXP * DIM; i += 256) s_rw[i] = rw[i];
    __syncthreads();
    int warp = threadIdx.x >> 5, lane = threadIdx.x & 31;
    int t = blockIdx.x * 8 + warp;
    const float* xr = x + (size_t)t * DIM;
    float acc[NEXP];
#pragma unroll
    for (int e = 0; e < NEXP; e++) acc[e] = 0.f;
    for (int j = lane; j < DIM; j += 32) {
        float xv = xr[j];
#pragma unroll
        for (int e = 0; e < NEXP; e++) acc[e] += xv * s_rw[e * DIM + j];
    }
#pragma unroll
    for (int e = 0; e < NEXP; e++)
#pragma unroll
        for (int o = 16; o > 0; o >>= 1)
            acc[e] += __shfl_down_sync(0xffffffff, acc[e], o);
    if (lane == 0) {
        float m = acc[0];
#pragma unroll
        for (int e = 1; e < NEXP; e++) m = fmaxf(m, acc[e]);
        float p[NEXP], s = 0.f;
#pragma unroll
        for (int e = 0; e < NEXP; e++) { p[e] = expf(acc[e] - m); s += p[e]; }
        float inv = 1.f / s;
#pragma unroll
        for (int e = 0; e < NEXP; e++) atomicAdd(&g_psum[e], p[e] * inv);
        int i1 = 0;
#pragma unroll
        for (int e = 1; e < NEXP; e++) if (acc[e] > acc[i1]) i1 = e;
        int i2 = (i1 == 0) ? 1 : 0;
#pragma unroll
        for (int e = 0; e < NEXP; e++)
            if (e != i1 && acc[e] > acc[i2]) i2 = e;
        float g1 = 1.f / (1.f + expf(acc[i2] - acc[i1]));
        float g2 = 1.f - g1;
        g_topk_idx[t*2+0] = i1;  g_topk_idx[t*2+1] = i2;
        g_topk_gate[t*2+0] = g1; g_topk_gate[t*2+1] = g2;
        atomicAdd(&g_counts[i1], 1);
        atomicAdd(&g_counts[i2], 1);
    }
}

__global__ void schedule_kernel(float* __restrict__ d_out, int write_aux) {
    if (threadIdx.x == 0) {
        int off = 0, nt = 0;
        for (int e = 0; e < NEXP; e++) {
            g_offsets[e] = off;
            int n = g_counts[e];
            for (int rs = 0; rs < n; rs += BM) {
                g_tile_expert[nt] = e;
                g_tile_row[nt]    = off + rs;
                g_tile_m[nt]      = min(BM, n - rs);
                nt++;
            }
            off += n;
        }
        g_ntiles = nt;
        if (write_aux) {
            float aux = 0.f;
            for (int e = 0; e < NEXP; e++)
                aux += ((float)g_counts[e] / (float)NROWS) * (g_psum[e] / (float)T_TOKENS);
            d_out[(size_t)T_TOKENS * DIM] = (float)NEXP * aux;
        }
    }
}

__global__ void scatter_kernel() {
    int t = blockIdx.x * 256 + threadIdx.x;
    if (t >= T_TOKENS) return;
#pragma unroll
    for (int k = 0; k < TOPK; k++) {
        int e   = g_topk_idx[t*2+k];
        int pos = atomicAdd(&g_cursor[e], 1);
        int r   = g_offsets[e] + pos;
        g_row_token[r]     = t;
        g_token_row[t*2+k] = r;
    }
}

// ---------------- grouped GEMM: mma.sync bf16 split x3, cp.async 3-stage ----------------
// L1:  hidden = gelu(x @ w1^T + b1) -> g_hhi/g_hlo (bf16 split)
// !L1: y      = hidden @ w2^T + b2  -> g_ybuf (fp32)
template <int KTOT, int NTOT, bool L1>
__global__ void __launch_bounds__(256, 1)
gemm_mma(const float* __restrict__ bias) {
    int tile = blockIdx.y;
    if (tile >= g_ntiles) return;
    int e     = g_tile_expert[tile];
    int row0  = g_tile_row[tile];
    int mrows = g_tile_m[tile];
    int n0    = blockIdx.x * BN;

    extern __shared__ char sm[];
    uint32_t sb = s2u(sm);

    int tid = threadIdx.x, lane = tid & 31, wid = tid >> 5;
    int wm = (wid & 1) * 64;
    int wn = (wid >> 1) * 32;

    const __nv_bfloat16* Ahi = L1 ? g_xhi : g_hhi;
    const __nv_bfloat16* Alo = L1 ? g_xlo : g_hlo;
    const __nv_bfloat16* Bhi = (L1 ? g_w1hi : g_w2hi) +
                               ((size_t)e * NTOT + n0) * KTOT;
    const __nv_bfloat16* Blo = (L1 ? g_w1lo : g_w2lo) +
                               ((size_t)e * NTOT + n0) * KTOT;
    const float* be = bias + (size_t)e * NTOT + n0;

    // per-thread cp.async items: 2 A row-chunks + 2 B row-chunks, 16B hi + 16B lo each
    size_t aoff[2], boff[2];
    uint32_t smoffA[2], smoffB[2];
    uint32_t asz[2];
#pragma unroll
    for (int t = 0; t < 2; t++) {
        {   // A: idx 0..511
            int idx = tid + 256 * t;
            int r = idx >> 2, c = idx & 3;
            bool ok = (r < mrows);
            size_t rowbase;
            if (L1) rowbase = ok ? (size_t)g_row_token[row0 + r] * KTOT : 0;
            else    rowbase = ok ? (size_t)(row0 + r) * KTOT : 0;
            aoff[t]   = rowbase + c * 8;
            smoffA[t] = (uint32_t)(r * ROWB + c * 16);
            asz[t]    = ok ? 16u : 0u;
        }
        {   // B: idx 512..1023
            int idx = tid + 256 * t + 512;
            int r = (idx - 512) >> 2, c = (idx - 512) & 3;
            boff[t]   = (size_t)r * KTOT + c * 8;
            smoffB[t] = (uint32_t)(r * ROWB + c * 16);
        }
    }

    auto issue_stage = [&](int s, int kc) {
        int k0 = kc * BK;
        uint32_t base = sb + s * STAGE;
#pragma unroll
        for (int t = 0; t < 2; t++) {
            CPASYNC16(base + smoffA[t],              Ahi + aoff[t] + k0, asz[t]);
            CPASYNC16(base + TILE_SZ + smoffA[t],    Alo + aoff[t] + k0, asz[t]);
            CPASYNC16(base + 2*TILE_SZ + smoffB[t],  Bhi + boff[t] + k0, 16u);
            CPASYNC16(base + 3*TILE_SZ + smoffB[t],  Blo + boff[t] + k0, 16u);
        }
    };

    float acc[4][4][4];
#pragma unroll
    for (int i = 0; i < 4; i++)
#pragma unroll
        for (int j = 0; j < 4; j++)
#pragma unroll
            for (int q = 0; q < 4; q++) acc[i][j][q] = 0.f;

    auto compute = [&](int s) {
        uint32_t Ab = sb + s * STAGE;
#pragma unroll
        for (int h = 0; h < 2; h++) {
            int cb = 2 * h + (lane >> 4);
            int rA = wm + (lane & 15);
            uint32_t ah[4][4], al[4][4];
#pragma unroll
            for (int i = 0; i < 4; i++) {
                uint32_t ad = Ab + (uint32_t)((rA + i * 16) * ROWB + cb * 16);
                LDSM4(ah[i], ad);
                LDSM4(al[i], ad + TILE_SZ);
            }
            int rB = wn + (lane & 15);
            uint32_t bh[2][4], bl[2][4];
#pragma unroll
            for (int j = 0; j < 2; j++) {
                uint32_t bd = Ab + 2 * TILE_SZ +
                              (uint32_t)((rB + j * 16) * ROWB + cb * 16);
                LDSM4(bh[j], bd);
                LDSM4(bl[j], bd + TILE_SZ);
            }
#pragma unroll
            for (int i = 0; i < 4; i++)
#pragma unroll
                for (int j = 0; j < 4; j++) {
                    int jj = j >> 1, ss = j & 1;
                    MMA16816(acc[i][j], ah[i], bh[jj][ss], bh[jj][ss + 2]);
                    MMA16816(acc[i][j], ah[i], bl[jj][ss], bl[jj][ss + 2]);
                    MMA16816(acc[i][j], al[i], bh[jj][ss], bh[jj][ss + 2]);
                }
        }
    };

    constexpr int NC = KTOT / BK;
    issue_stage(0, 0); CPCOMMIT();
    issue_stage(1, 1); CPCOMMIT();
    for (int c = 0; c < NC; c++) {
        CPWAIT1();
        __syncthreads();
        compute(c % NSTAGE);
        if (c + 2 < NC) issue_stage((c + 2) % NSTAGE, c + 2);
        CPCOMMIT();
    }

    // ---- epilogue ----
#pragma unroll
    for (int j = 0; j < 4; j++) {
        int colw = wn + j * 8 + 2 * (lane & 3);
        float b0 = __ldg(be + colw);
        float b1 = __ldg(be + colw + 1);
#pragma unroll
        for (int i = 0; i < 4; i++) {
#pragma unroll
            for (int rh = 0; rh < 2; rh++) {
                int m = wm + i * 16 + (lane >> 2) + rh * 8;
                if (m >= mrows) continue;
                float v0 = acc[i][j][rh * 2 + 0] + b0;
                float v1 = acc[i][j][rh * 2 + 1] + b1;
                size_t gbase = (size_t)(row0 + m) * NTOT + n0 + colw;
                if (L1) {
                    v0 = gelu_exact(v0);
                    v1 = gelu_exact(v1);
                    uint32_t h0 = (uint32_t)__bfloat16_as_ushort(__float2bfloat16(v0));
                    float r0f = v0 - __uint_as_float(h0 << 16);
                    uint32_t l0 = (uint32_t)__bfloat16_as_ushort(__float2bfloat16(r0f));
                    uint32_t h1 = (uint32_t)__bfloat16_as_ushort(__float2bfloat16(v1));
                    float r1f = v1 - __uint_as_float(h1 << 16);
                    uint32_t l1 = (uint32_t)__bfloat16_as_ushort(__float2bfloat16(r1f));
                    *(uint32_t*)(g_hhi + gbase) = h0 | (h1 << 16);
                    *(uint32_t*)(g_hlo + gbase) = l0 | (l1 << 16);
                } else {
                    *(float2*)(g_ybuf + gbase) = make_float2(v0, v1);
                }
            }
        }
    }
}

// ---------------- deterministic gated combine ----------------
__global__ void combine_kernel(float* __restrict__ out) {
    int t = blockIdx.x;
    int r0 = g_token_row[t*2+0], r1 = g_token_row[t*2+1];
    float g0 = g_topk_gate[t*2+0], g1 = g_topk_gate[t*2+1];
    const float* y0 = g_ybuf + (size_t)r0 * DIM;
    const float* y1 = g_ybuf + (size_t)r1 * DIM;
    float* o = out + (size_t)t * DIM;
    for (int c = threadIdx.x; c < DIM; c += 256)
        o[c] = g0 * y0[c] + g1 * y1[c];
}

// ---------------- launch ----------------
extern "C" void kernel_launch(void* const* d_in, const int* in_sizes, int n_in,
                              void* d_out, int out_size) {
    const float* x  = (const float*)d_in[0];
    const float* rw = (const float*)d_in[1];
    const float* w1 = (const float*)d_in[2];
    const float* b1 = (const float*)d_in[3];
    const float* w2 = (const float*)d_in[4];
    const float* b2 = (const float*)d_in[5];
    float* out = (float*)d_out;

    int write_aux = (out_size > T_TOKENS * DIM) ? 1 : 0;

    // idempotent, capture-safe, no static guard (determinism rule)
    cudaFuncSetAttribute(gemm_mma<DIM, HIDDEN, true>,
                         cudaFuncAttributeMaxDynamicSharedMemorySize, SMEM_DYN);
    cudaFuncSetAttribute(gemm_mma<HIDDEN, DIM, false>,
                         cudaFuncAttributeMaxDynamicSharedMemorySize, SMEM_DYN);

    init_kernel<<<1, 32>>>();
    router_kernel<<<T_TOKENS / 8, 256>>>(x, rw);
    split_kernel<<<592, 256>>>((const float4*)w1, 0, NEXP * HIDDEN * DIM / 4);
    split_kernel<<<592, 256>>>((const float4*)w2, 1, NEXP * DIM * HIDDEN / 4);
    split_kernel<<<592, 256>>>((const float4*)x,  2, T_TOKENS * DIM / 4);
    schedule_kernel<<<1, 32>>>(out, write_aux);
    scatter_kernel<<<(T_TOKENS + 255) / 256, 256>>>();
    gemm_mma<DIM, HIDDEN, true><<<dim3(HIDDEN / BN, MAXTILES), 256, SMEM_DYN>>>(b1);
    gemm_mma<HIDDEN, DIM, false><<<dim3(DIM / BN, MAXTILES), 256, SMEM_DYN>>>(b2);
    combine_kernel<<<T_TOKENS, 256>>>(out);
}

// round 12
// speedup vs baseline: 2.4773x; 2.4773x over previous
#include <cuda_runtime.h>
#include <cuda_fp16.h>
#include <math.h>
#include <stdint.h>

#define T_TOKENS   8192
#define DIM        1024
#define HIDDEN     2048
#define NEXP       8
#define TOPK       2
#define NROWS      (T_TOKENS * TOPK)   // 16384

#define BM 128
#define BN 128
#define BK 32                      // fp16 k-elements per stage
#define ROWB 80                    // padded row stride (64B data + 16B pad)
#define TILE_SZ (BM * ROWB)        // 10240 B per operand tile
#define STAGE   (2 * TILE_SZ)      // A, B
#define NSTAGE  3
#define SMEM_DYN (NSTAGE * STAGE)  // 61440 B
#define MAXTILES 136

// ---------------- scratch ----------------
__device__ __half g_w1h[(size_t)NEXP * HIDDEN * DIM];
__device__ __half g_w2h[(size_t)NEXP * DIM * HIDDEN];
__device__ __half g_xh[(size_t)T_TOKENS * DIM];
__device__ __half g_hh[(size_t)NROWS * HIDDEN];
__device__ float  g_ybuf[(size_t)NROWS * DIM];
__device__ int   g_counts[NEXP];
__device__ int   g_cursor[NEXP];
__device__ int   g_offsets[NEXP];
__device__ float g_psum[NEXP];
__device__ int   g_topk_idx[T_TOKENS * TOPK];
__device__ float g_topk_gate[T_TOKENS * TOPK];
__device__ int   g_row_token[NROWS];
__device__ int   g_token_row[T_TOKENS * TOPK];
__device__ int   g_tile_expert[MAXTILES];
__device__ int   g_tile_row[MAXTILES];
__device__ int   g_tile_m[MAXTILES];
__device__ int   g_ntiles;

// ---------------- helpers ----------------
__device__ __forceinline__ uint32_t s2u(const void* p) {
    uint32_t a;
    asm("{ .reg .u64 t; cvta.to.shared.u64 t, %1; cvt.u32.u64 %0, t; }" : "=r"(a) : "l"(p));
    return a;
}

#define LDSM4(r, addr) \
    asm volatile("ldmatrix.sync.aligned.m8n8.x4.shared.b16 {%0,%1,%2,%3}, [%4];" \
        : "=r"((r)[0]), "=r"((r)[1]), "=r"((r)[2]), "=r"((r)[3]) : "r"(addr) : "memory")

#define MMA16816F16(d, a, b0, b1) \
    asm volatile("mma.sync.aligned.m16n8k16.row.col.f32.f16.f16.f32 " \
        "{%0,%1,%2,%3}, {%4,%5,%6,%7}, {%8,%9}, {%0,%1,%2,%3};" \
        : "+f"((d)[0]), "+f"((d)[1]), "+f"((d)[2]), "+f"((d)[3]) \
        : "r"((a)[0]), "r"((a)[1]), "r"((a)[2]), "r"((a)[3]), "r"(b0), "r"(b1))

#define CPASYNC16(saddr, gptr, sz) \
    asm volatile("cp.async.cg.shared.global [%0], [%1], 16, %2;" \
        :: "r"(saddr), "l"(gptr), "r"(sz) : "memory")
#define CPCOMMIT() asm volatile("cp.async.commit_group;" ::: "memory")
#define CPWAIT1()  asm volatile("cp.async.wait_group 1;" ::: "memory")

__device__ __forceinline__ float gelu_exact(float v) {
    return 0.5f * v * (1.f + erff(v * 0.70710678118654752f));
}

// ---------------- convert fp32 -> fp16 ----------------
// which: 0=w1, 1=w2, 2=x
__global__ void conv_kernel(const float4* __restrict__ src, int which, int n4) {
    __half* dh;
    if (which == 0)      dh = g_w1h;
    else if (which == 1) dh = g_w2h;
    else                 dh = g_xh;
    int stride = gridDim.x * blockDim.x;
    for (int i = blockIdx.x * blockDim.x + threadIdx.x; i < n4; i += stride) {
        float4 f = src[i];
        __half2 p0 = __floats2half2_rn(f.x, f.y);
        __half2 p1 = __floats2half2_rn(f.z, f.w);
        *(uint2*)(dh + (size_t)i * 4) =
            make_uint2(*(uint32_t*)&p0, *(uint32_t*)&p1);
    }
}

// ---------------- small kernels (verified passing, unchanged) ----------------
__global__ void init_kernel() {
    int i = threadIdx.x;
    if (i < NEXP) { g_counts[i] = 0; g_cursor[i] = 0; g_psum[i] = 0.f; }
}

__global__ void router_kernel(const float* __restrict__ x,
                              const float* __restrict__ rw) {
    __shared__ float s_rw[NEXP * DIM];
    for (int i = threadIdx.x; i < NEXP * DIM; i += 256) s_rw[i] = rw[i];
    __syncthreads();
    int warp = threadIdx.x >> 5, lane = threadIdx.x & 31;
    int t = blockIdx.x * 8 + warp;
    const float* xr = x + (size_t)t * DIM;
    float acc[NEXP];
#pragma unroll
    for (int e = 0; e < NEXP; e++) acc[e] = 0.f;
    for (int j = lane; j < DIM; j += 32) {
        float xv = xr[j];
#pragma unroll
        for (int e = 0; e < NEXP; e++) acc[e] += xv * s_rw[e * DIM + j];
    }
#pragma unroll
    for (int e = 0; e < NEXP; e++)
#pragma unroll
        for (int o = 16; o > 0; o >>= 1)
            acc[e] += __shfl_down_sync(0xffffffff, acc[e], o);
    if (lane == 0) {
        float m = acc[0];
#pragma unroll
        for (int e = 1; e < NEXP; e++) m = fmaxf(m, acc[e]);
        float p[NEXP], s = 0.f;
#pragma unroll
        for (int e = 0; e < NEXP; e++) { p[e] = expf(acc[e] - m); s += p[e]; }
        float inv = 1.f / s;
#pragma unroll
        for (int e = 0; e < NEXP; e++) atomicAdd(&g_psum[e], p[e] * inv);
        int i1 = 0;
#pragma unroll
        for (int e = 1; e < NEXP; e++) if (acc[e] > acc[i1]) i1 = e;
        int i2 = (i1 == 0) ? 1 : 0;
#pragma unroll
        for (int e = 0; e < NEXP; e++)
            if (e != i1 && acc[e] > acc[i2]) i2 = e;
        float g1 = 1.f / (1.f + expf(acc[i2] - acc[i1]));
        float g2 = 1.f - g1;
        g_topk_idx[t*2+0] = i1;  g_topk_idx[t*2+1] = i2;
        g_topk_gate[t*2+0] = g1; g_topk_gate[t*2+1] = g2;
        atomicAdd(&g_counts[i1], 1);
        atomicAdd(&g_counts[i2], 1);
    }
}

__global__ void schedule_kernel(float* __restrict__ d_out, int write_aux) {
    if (threadIdx.x == 0) {
        int off = 0, nt = 0;
        for (int e = 0; e < NEXP; e++) {
            g_offsets[e] = off;
            int n = g_counts[e];
            for (int rs = 0; rs < n; rs += BM) {
                g_tile_expert[nt] = e;
                g_tile_row[nt]    = off + rs;
                g_tile_m[nt]      = min(BM, n - rs);
                nt++;
            }
            off += n;
        }
        g_ntiles = nt;
        if (write_aux) {
            float aux = 0.f;
            for (int e = 0; e < NEXP; e++)
                aux += ((float)g_counts[e] / (float)NROWS) * (g_psum[e] / (float)T_TOKENS);
            d_out[(size_t)T_TOKENS * DIM] = (float)NEXP * aux;
        }
    }
}

__global__ void scatter_kernel() {
    int t = blockIdx.x * 256 + threadIdx.x;
    if (t >= T_TOKENS) return;
#pragma unroll
    for (int k = 0; k < TOPK; k++) {
        int e   = g_topk_idx[t*2+k];
        int pos = atomicAdd(&g_cursor[e], 1);
        int r   = g_offsets[e] + pos;
        g_row_token[r]     = t;
        g_token_row[t*2+k] = r;
    }
}

// ---------------- grouped GEMM: mma.sync fp16, fp32 accum, cp.async 3-stage ----------------
// L1:  hidden = gelu(x @ w1^T + b1) -> g_hh (fp16)
// !L1: y      = hidden @ w2^T + b2  -> g_ybuf (fp32)
template <int KTOT, int NTOT, bool L1>
__global__ void __launch_bounds__(256, 2)
gemm_mma(const float* __restrict__ bias) {
    int tile = blockIdx.y;
    if (tile >= g_ntiles) return;
    int e     = g_tile_expert[tile];
    int row0  = g_tile_row[tile];
    int mrows = g_tile_m[tile];
    int n0    = blockIdx.x * BN;

    extern __shared__ char sm[];
    uint32_t sb = s2u(sm);

    int tid = threadIdx.x, lane = tid & 31, wid = tid >> 5;
    int wm = (wid & 1) * 64;
    int wn = (wid >> 1) * 32;

    const __half* A = L1 ? g_xh : g_hh;
    const __half* B = (L1 ? g_w1h : g_w2h) + ((size_t)e * NTOT + n0) * KTOT;
    const float* be = bias + (size_t)e * NTOT + n0;

    // per-thread cp.async items: 2 A row-chunks + 2 B row-chunks, 16B each
    size_t aoff[2], boff[2];
    uint32_t smoffA[2], smoffB[2];
    uint32_t asz[2];
#pragma unroll
    for (int t = 0; t < 2; t++) {
        {   // A: idx 0..511 -> (row, 16B chunk)
            int idx = tid + 256 * t;
            int r = idx >> 2, c = idx & 3;
            bool ok = (r < mrows);
            size_t rowbase;
            if (L1) rowbase = ok ? (size_t)g_row_token[row0 + r] * KTOT : 0;
            else    rowbase = ok ? (size_t)(row0 + r) * KTOT : 0;
            aoff[t]   = rowbase + c * 8;
            smoffA[t] = (uint32_t)(r * ROWB + c * 16);
            asz[t]    = ok ? 16u : 0u;   // zero-fill OOB rows
        }
        {   // B
            int idx = tid + 256 * t;
            int r = idx >> 2, c = idx & 3;
            boff[t]   = (size_t)r * KTOT + c * 8;
            smoffB[t] = (uint32_t)(r * ROWB + c * 16);
        }
    }

    auto issue_stage = [&](int s, int kc) {
        int k0 = kc * BK;
        uint32_t base = sb + s * STAGE;
#pragma unroll
        for (int t = 0; t < 2; t++) {
            CPASYNC16(base + smoffA[t],           A + aoff[t] + k0, asz[t]);
            CPASYNC16(base + TILE_SZ + smoffB[t], B + boff[t] + k0, 16u);
        }
    };

    float acc[4][4][4];
#pragma unroll
    for (int i = 0; i < 4; i++)
#pragma unroll
        for (int j = 0; j < 4; j++)
#pragma unroll
            for (int q = 0; q < 4; q++) acc[i][j][q] = 0.f;

    auto compute = [&](int s) {
        uint32_t Ab = sb + s * STAGE;
#pragma unroll
        for (int h = 0; h < 2; h++) {       // two k16 halves of BK=32
            int cb = 2 * h + (lane >> 4);
            int rA = wm + (lane & 15);
            uint32_t ah[4][4];
#pragma unroll
            for (int i = 0; i < 4; i++) {
                uint32_t ad = Ab + (uint32_t)((rA + i * 16) * ROWB + cb * 16);
                LDSM4(ah[i], ad);
            }
            int rB = wn + (lane & 15);
            uint32_t bh[2][4];
#pragma unroll
            for (int j = 0; j < 2; j++) {
                uint32_t bd = Ab + TILE_SZ +
                              (uint32_t)((rB + j * 16) * ROWB + cb * 16);
                LDSM4(bh[j], bd);
            }
#pragma unroll
            for (int i = 0; i < 4; i++)
#pragma unroll
                for (int j = 0; j < 4; j++) {
                    int jj = j >> 1, ss = j & 1;
                    MMA16816F16(acc[i][j], ah[i], bh[jj][ss], bh[jj][ss + 2]);
                }
        }
    };

    constexpr int NC = KTOT / BK;
    issue_stage(0, 0); CPCOMMIT();
    issue_stage(1, 1); CPCOMMIT();
    for (int c = 0; c < NC; c++) {
        CPWAIT1();
        __syncthreads();
        compute(c % NSTAGE);
        if (c + 2 < NC) issue_stage((c + 2) % NSTAGE, c + 2);
        CPCOMMIT();
    }

    // ---- epilogue: bias (+gelu for L1), direct register -> gmem ----
#pragma unroll
    for (int j = 0; j < 4; j++) {
        int colw = wn + j * 8 + 2 * (lane & 3);
        float b0 = __ldg(be + colw);
        float b1 = __ldg(be + colw + 1);
#pragma unroll
        for (int i = 0; i < 4; i++) {
#pragma unroll
            for (int rh = 0; rh < 2; rh++) {
                int m = wm + i * 16 + (lane >> 2) + rh * 8;
                if (m >= mrows) continue;
                float v0 = acc[i][j][rh * 2 + 0] + b0;
                float v1 = acc[i][j][rh * 2 + 1] + b1;
                size_t gbase = (size_t)(row0 + m) * NTOT + n0 + colw;
                if (L1) {
                    v0 = gelu_exact(v0);
                    v1 = gelu_exact(v1);
                    __half2 p = __floats2half2_rn(v0, v1);
                    *(uint32_t*)(g_hh + gbase) = *(uint32_t*)&p;
                } else {
                    *(float2*)(g_ybuf + gbase) = make_float2(v0, v1);
                }
            }
        }
    }
}

// ---------------- deterministic gated combine ----------------
__global__ void combine_kernel(float* __restrict__ out) {
    int t = blockIdx.x;
    int r0 = g_token_row[t*2+0], r1 = g_token_row[t*2+1];
    float g0 = g_topk_gate[t*2+0], g1 = g_topk_gate[t*2+1];
    const float* y0 = g_ybuf + (size_t)r0 * DIM;
    const float* y1 = g_ybuf + (size_t)r1 * DIM;
    float* o = out + (size_t)t * DIM;
    for (int c = threadIdx.x; c < DIM; c += 256)
        o[c] = g0 * y0[c] + g1 * y1[c];
}

// ---------------- launch ----------------
extern "C" void kernel_launch(void* const* d_in, const int* in_sizes, int n_in,
                              void* d_out, int out_size) {
    const float* x  = (const float*)d_in[0];
    const float* rw = (const float*)d_in[1];
    const float* w1 = (const float*)d_in[2];
    const float* b1 = (const float*)d_in[3];
    const float* w2 = (const float*)d_in[4];
    const float* b2 = (const float*)d_in[5];
    float* out = (float*)d_out;

    int write_aux = (out_size > T_TOKENS * DIM) ? 1 : 0;

    // idempotent, capture-safe, no static guard (determinism rule)
    cudaFuncSetAttribute(gemm_mma<DIM, HIDDEN, true>,
                         cudaFuncAttributeMaxDynamicSharedMemorySize, SMEM_DYN);
    cudaFuncSetAttribute(gemm_mma<HIDDEN, DIM, false>,
                         cudaFuncAttributeMaxDynamicSharedMemorySize, SMEM_DYN);

    init_kernel<<<1, 32>>>();
    router_kernel<<<T_TOKENS / 8, 256>>>(x, rw);
    conv_kernel<<<592, 256>>>((const float4*)w1, 0, NEXP * HIDDEN * DIM / 4);
    conv_kernel<<<592, 256>>>((const float4*)w2, 1, NEXP * DIM * HIDDEN / 4);
    conv_kernel<<<592, 256>>>((const float4*)x,  2, T_TOKENS * DIM / 4);
    schedule_kernel<<<1, 32>>>(out, write_aux);
    scatter_kernel<<<(T_TOKENS + 255) / 256, 256>>>();
    gemm_mma<DIM, HIDDEN, true><<<dim3(HIDDEN / BN, MAXTILES), 256, SMEM_DYN>>>(b1);
    gemm_mma<HIDDEN, DIM, false><<<dim3(DIM / BN, MAXTILES), 256, SMEM_DYN>>>(b2);
    combine_kernel<<<T_TOKENS, 256>>>(out);
}